// round 16
// baseline (speedup 1.0000x reference)
#include <cuda_runtime.h>
#include <math.h>

#define B_ 16
#define N_ 16384
#define SPLIT_ 8
#define TILES_ 16
#define SLOT_ (64 + 2*64*64)
#define FULLM 0xffffffffu

typedef unsigned u32; typedef unsigned short u16;

__device__ __align__(16) float g_part[(size_t)B_*SPLIT_*SLOT_];
__device__ int g_cnt[B_];   // zero-init at load; last CTA resets to 0 each launch

// strides (bytes)
#define PSTR 144
#define XSTR 144
#define QSTR 272
// shared offsets (bytes)
#define O_IVHH 0
#define O_IVHL 9216
#define O_AAH  18432
#define O_AAL  27648
#define O_XA   36864          /* X buffer A: XH,XL,X2H,X2L each 18432 */
#define O_XB   110592         /* X buffer B */
#define O_QT   184320         /* Q tile [p][k-hi 128B | k-lo 128B] */
#define O_CC   219136
#define O_QP   219392
#define SMEMSZ 221440

__device__ __forceinline__ u32 smem_u32(const void* p){u32 a;asm("{ .reg .u64 t; cvta.to.shared.u64 t, %1; cvt.u32.u64 %0, t; }":"=r"(a):"l"(p));return a;}
// pack: lo16 = bf16(a), hi16 = bf16(b)
__device__ __forceinline__ u32 cvt2(float b, float a){u32 r;asm("cvt.rn.satfinite.bf16x2.f32 %0, %1, %2;":"=r"(r):"f"(b),"f"(a));return r;}
__device__ __forceinline__ float hil(u32 h){return __uint_as_float(h<<16);}
__device__ __forceinline__ float hih(u32 h){return __uint_as_float(h&0xffff0000u);}
#define STS32(a,v) asm volatile("st.shared.b32 [%0], %1;"::"r"(a),"r"(v):"memory")
#define STS64(a,v0,v1) asm volatile("st.shared.v2.b32 [%0], {%1,%2};"::"r"(a),"r"(v0),"r"(v1):"memory")
#define LDSM4(ad,r0,r1,r2,r3)  asm volatile("ldmatrix.sync.aligned.m8n8.x4.shared.b16 {%0,%1,%2,%3}, [%4];":"=r"(r0),"=r"(r1),"=r"(r2),"=r"(r3):"r"(ad))
#define LDSM4T(ad,r0,r1,r2,r3) asm volatile("ldmatrix.sync.aligned.m8n8.x4.trans.shared.b16 {%0,%1,%2,%3}, [%4];":"=r"(r0),"=r"(r1),"=r"(r2),"=r"(r3):"r"(ad))
#define MMA(c,A0,A1,A2,A3,B0,B1) asm("mma.sync.aligned.m16n8k16.row.col.f32.bf16.bf16.f32 " \
    "{%0,%1,%2,%3}, {%4,%5,%6,%7}, {%8,%9}, {%0,%1,%2,%3};" \
    :"+f"((c)[0]),"+f"((c)[1]),"+f"((c)[2]),"+f"((c)[3]) \
    :"r"(A0),"r"(A1),"r"(A2),"r"(A3),"r"(B0),"r"(B1))

__global__ __launch_bounds__(256,1) void fv_main(
    const float* __restrict__ x, const float* __restrict__ pi,
    const float* __restrict__ mu, const float* __restrict__ var,
    float* __restrict__ out)
{
    extern __shared__ char sm[];
    const u32 sb = smem_u32(sm);
    const int tid = threadIdx.x, wid = tid>>5, lane = tid&31;
    const int b = blockIdx.y, s = blockIdx.x;
    const int tg = lane&3, g = lane>>2;
    const int l15 = lane&15, l7 = lane&7, lh = lane>>4, lq = (lane>>3)&1;
    float* ccs = (float*)(sm + O_CC);

    const size_t xoff = ((size_t)b*N_ + (size_t)s*(N_/SPLIT_))*64;
    const float4* xg4 = (const float4*)(x + xoff);

    // prologue LDG for tile 0
    float4 Pf[8];
    #pragma unroll
    for (int ii=0;ii<8;++ii) Pf[ii] = xg4[tid + 256*ii];

    // ---- stage params: [k][d] bf16 hi/lo for IVH(-0.5/var) and AA(mu/var) ----
    {
        int k = tid>>2, d0 = (tid&3)*16;
        #pragma unroll
        for (int j=0;j<4;++j){
            float4 vv = *(const float4*)(var + k*64 + d0 + 4*j);
            float4 mm = *(const float4*)(mu  + k*64 + d0 + 4*j);
            float i0=1.f/vv.x, i1=1.f/vv.y, i2=1.f/vv.z, i3=1.f/vv.w;
            float h0=-0.5f*i0, h1=-0.5f*i1, h2=-0.5f*i2, h3=-0.5f*i3;
            float a0=mm.x*i0, a1=mm.y*i1, a2=mm.z*i2, a3=mm.w*i3;
            u32 off = (u32)(k*PSTR + (d0+4*j)*2);
            u32 p01=cvt2(h1,h0), p23=cvt2(h3,h2);
            STS64(sb+O_IVHH+off, p01, p23);
            STS64(sb+O_IVHL+off, cvt2(h1-hih(p01),h0-hil(p01)), cvt2(h3-hih(p23),h2-hil(p23)));
            u32 q01=cvt2(a1,a0), q23=cvt2(a3,a2);
            STS64(sb+O_AAH+off, q01, q23);
            STS64(sb+O_AAL+off, cvt2(a1-hih(q01),a0-hil(q01)), cvt2(a3-hih(q23),a2-hil(q23)));
        }
    }
    if (tid < 64){
        float acc = 0.0f;
        for (int d=0; d<64; ++d){
            float v = var[tid*64+d], m = mu[tid*64+d];
            acc += logf(v) + m*m/v;
        }
        ccs[tid] = logf(pi[tid]) - 0.5f*(64.0f*1.83787706640934548356f + acc);
    }

    // ---- stage tile 0 into buffer A ----
    #pragma unroll
    for (int ii=0;ii<8;++ii){
        int i = tid + 256*ii;
        u32 ha = (u32)((i>>4)*XSTR + (i&15)*8);
        float4 v = Pf[ii];
        u32 h01=cvt2(v.y,v.x), h23=cvt2(v.w,v.z);
        STS64(sb+O_XA+ha, h01, h23);
        STS64(sb+O_XA+18432+ha, cvt2(v.y-hih(h01),v.x-hil(h01)), cvt2(v.w-hih(h23),v.z-hil(h23)));
        float sx=v.x*v.x, sy=v.y*v.y, sz=v.z*v.z, sw=v.w*v.w;
        u32 s01=cvt2(sy,sx), s23=cvt2(sw,sz);
        STS64(sb+O_XA+36864+ha, s01, s23);
        STS64(sb+O_XA+55296+ha, cvt2(sy-hih(s01),sx-hil(s01)), cvt2(sw-hih(s23),sz-hil(s23)));
    }
    // prologue LDG for tile 1
    #pragma unroll
    for (int ii=0;ii<8;++ii) Pf[ii] = xg4[2048 + tid + 256*ii];
    __syncthreads();

    float ccr[16];
    #pragma unroll
    for (int i=0;i<16;++i) ccr[i] = ccs[(i>>1)*8 + tg*2 + (i&1)];

    // phase-2 warp roles: mw = k-half (0: k0-31, 1: k32-63), nw = col slice
    const int mw = wid>>2, nw = wid&3;

    float acc2[2][4][4];   // [mtp][cn*2+h][4] — hi/lo chained into same acc
    #pragma unroll
    for (int m=0;m<2;++m)
        #pragma unroll
        for (int n=0;n<4;++n){acc2[m][n][0]=0;acc2[m][n][1]=0;acc2[m][n][2]=0;acc2[m][n][3]=0;}
    float qacc[16];
    #pragma unroll
    for (int i=0;i<16;++i) qacc[i]=0;

    // per-thread ldmatrix offsets
    const u32 xa_off = (u32)((16*wid + l15)*XSTR + lh*16);               // phase-1 A (non-trans)
    const u32 pb_off = (u32)((l7 + lh*8)*PSTR + lq*16);                  // phase-1 B (non-trans)
    const u32 qa_off = sb + O_QT + (u32)((l7 + lh*8)*QSTR + lq*16);      // phase-2 A (trans)
    const u32 xb_off = (u32)(l15*XSTR + 64*(nw&1) + lh*16);              // phase-2 B (trans), 32 d-cols
    const u32 x2sel = (nw>>1)? 36864u : 0u;                               // nw 0,1 -> X ; 2,3 -> X2
    const u32 qcolh = (u32)(64*mw);                                       // Qhi col byte base

    for (int tile=0; tile<TILES_; ++tile){
        const u32 bufC = sb + ((tile&1)? O_XB : O_XA);
        const u32 bufN = sb + ((tile&1)? O_XA : O_XB);

        // ---- phase 1: logits, 3-term compensated ----
        float c1[8][4];
        #pragma unroll
        for (int i=0;i<8;++i){c1[i][0]=0;c1[i][1]=0;c1[i][2]=0;c1[i][3]=0;}
        #pragma unroll
        for (int ch=0; ch<2; ++ch){
            const u32 Ah = bufC + (ch? 0u : 36864u) + xa_off;  // ch0: X2, ch1: X
            const u32 Al = Ah + 18432u;
            const u32 Bh = sb + (ch? O_AAH : O_IVHH) + pb_off;
            const u32 Bl = Bh + 9216u;
            #pragma unroll
            for (int ks=0; ks<4; ++ks){
                u32 a0,a1,a2,a3, e0,e1,e2,e3;
                LDSM4(Ah + ks*32, a0,a1,a2,a3);
                LDSM4(Al + ks*32, e0,e1,e2,e3);
                #pragma unroll
                for (int n2=0;n2<4;++n2){
                    u32 b0,b1,b2,b3; LDSM4(Bh + n2*16*PSTR + ks*32, b0,b1,b2,b3);
                    MMA(c1[2*n2],   a0,a1,a2,a3, b0,b1);
                    MMA(c1[2*n2+1], a0,a1,a2,a3, b2,b3);
                    MMA(c1[2*n2],   e0,e1,e2,e3, b0,b1);
                    MMA(c1[2*n2+1], e0,e1,e2,e3, b2,b3);
                }
                #pragma unroll
                for (int n2=0;n2<4;++n2){
                    u32 b0,b1,b2,b3; LDSM4(Bl + n2*16*PSTR + ks*32, b0,b1,b2,b3);
                    MMA(c1[2*n2],   a0,a1,a2,a3, b0,b1);
                    MMA(c1[2*n2+1], a0,a1,a2,a3, b2,b3);
                }
            }
        }

        // ---- softmax: thread holds 2 points x 16 k ----
        #pragma unroll
        for (int r=0;r<2;++r){
            float v[16];
            #pragma unroll
            for (int i=0;i<16;++i) v[i] = c1[i>>1][(r<<1)|(i&1)] + ccr[i];
            float m0=fmaxf(v[0],v[1]), m1=fmaxf(v[2],v[3]), m2=fmaxf(v[4],v[5]), m3=fmaxf(v[6],v[7]);
            float m4=fmaxf(v[8],v[9]), m5=fmaxf(v[10],v[11]), m6=fmaxf(v[12],v[13]), m7=fmaxf(v[14],v[15]);
            float mx = fmaxf(fmaxf(fmaxf(m0,m1),fmaxf(m2,m3)), fmaxf(fmaxf(m4,m5),fmaxf(m6,m7)));
            mx = fmaxf(mx, __shfl_xor_sync(FULLM, mx, 1));
            mx = fmaxf(mx, __shfl_xor_sync(FULLM, mx, 2));
            #pragma unroll
            for (int i=0;i<16;++i) v[i] = __expf(v[i] - mx);
            float s0=v[0]+v[1], s1=v[2]+v[3], s2=v[4]+v[5], s3=v[6]+v[7];
            float s4=v[8]+v[9], s5=v[10]+v[11], s6=v[12]+v[13], s7=v[14]+v[15];
            float sum = ((s0+s1)+(s2+s3)) + ((s4+s5)+(s6+s7));
            sum += __shfl_xor_sync(FULLM, sum, 1);
            sum += __shfl_xor_sync(FULLM, sum, 2);
            float inv = __fdividef(1.0f, sum);
            #pragma unroll
            for (int i=0;i<16;++i){
                float q = v[i]*inv;
                qacc[i] += q;
                c1[i>>1][(r<<1)|(i&1)] = q;
            }
        }

        __syncthreads();   // phase-2(t-1) done / X buffers settled

        // ---- stage next tile into the other buffer ----
        if (tile+1 < TILES_){
            #pragma unroll
            for (int ii=0;ii<8;++ii){
                int i = tid + 256*ii;
                u32 ha = (u32)((i>>4)*XSTR + (i&15)*8);
                float4 v = Pf[ii];
                u32 h01=cvt2(v.y,v.x), h23=cvt2(v.w,v.z);
                STS64(bufN+ha, h01, h23);
                STS64(bufN+18432+ha, cvt2(v.y-hih(h01),v.x-hil(h01)), cvt2(v.w-hih(h23),v.z-hil(h23)));
                float sx=v.x*v.x, sy=v.y*v.y, sz=v.z*v.z, sw=v.w*v.w;
                u32 s01=cvt2(sy,sx), s23=cvt2(sw,sz);
                STS64(bufN+36864+ha, s01, s23);
                STS64(bufN+55296+ha, cvt2(sy-hih(s01),sx-hil(s01)), cvt2(sw-hih(s23),sz-hil(s23)));
            }
        }
        // ---- Q store: [p][k] rows, hi at +0, lo at +128 ----
        #pragma unroll
        for (int r=0;r<2;++r){
            u32 qrow = sb + O_QT + (u32)((16*wid + g + 8*r)*QSTR + tg*4);
            #pragma unroll
            for (int j=0;j<8;++j){
                float qe = c1[j][(r<<1)], qo = c1[j][(r<<1)|1];
                u32 h = cvt2(qo, qe);
                STS32(qrow + j*16, h);
                STS32(qrow + 128 + j*16, cvt2(qo-hih(h), qe-hil(h)));
            }
        }
        // LDG for tile t+2
        if (tile+2 < TILES_){
            #pragma unroll
            for (int ii=0;ii<8;++ii) Pf[ii] = xg4[(tile+2)*2048 + tid + 256*ii];
        }
        __syncthreads();   // QT + next X buffer published

        // ---- phase 2: warp (mw,nw): 32 k-rows x 32 d-cols, hi/lo chained ----
        const u32 xbh = bufC + x2sel + xb_off;
        const u32 xbl = xbh + 18432u;
        #pragma unroll
        for (int ks=0;ks<8;++ks){
            u32 bh[2][4], bl[2][4];
            #pragma unroll
            for (int cn=0;cn<2;++cn){
                LDSM4T(xbh + ks*16*XSTR + cn*32, bh[cn][0],bh[cn][1],bh[cn][2],bh[cn][3]);
                LDSM4T(xbl + ks*16*XSTR + cn*32, bl[cn][0],bl[cn][1],bl[cn][2],bl[cn][3]);
            }
            #pragma unroll
            for (int mtp=0;mtp<2;++mtp){
                u32 ah0,ah1,ah2,ah3, al0,al1,al2,al3;
                u32 colh = qcolh + (u32)(32*mtp);
                LDSM4T(qa_off + ks*16*QSTR + colh,       ah0,ah1,ah2,ah3);
                LDSM4T(qa_off + ks*16*QSTR + 128 + colh, al0,al1,al2,al3);
                #pragma unroll
                for (int cn=0;cn<2;++cn){
                    MMA(acc2[mtp][cn*2],   ah0,ah1,ah2,ah3, bh[cn][0],bh[cn][1]);
                    MMA(acc2[mtp][cn*2+1], ah0,ah1,ah2,ah3, bh[cn][2],bh[cn][3]);
                    MMA(acc2[mtp][cn*2],   al0,al1,al2,al3, bh[cn][0],bh[cn][1]);
                    MMA(acc2[mtp][cn*2+1], al0,al1,al2,al3, bh[cn][2],bh[cn][3]);
                    MMA(acc2[mtp][cn*2],   ah0,ah1,ah2,ah3, bl[cn][0],bl[cn][1]);
                    MMA(acc2[mtp][cn*2+1], ah0,ah1,ah2,ah3, bl[cn][2],bl[cn][3]);
                }
            }
        }
    }

    // ---- Qsum: shuffle-reduce across g, stage per warp, reduce ----
    #pragma unroll
    for (int i=0;i<16;++i){
        qacc[i] += __shfl_xor_sync(FULLM, qacc[i], 4);
        qacc[i] += __shfl_xor_sync(FULLM, qacc[i], 8);
        qacc[i] += __shfl_xor_sync(FULLM, qacc[i], 16);
    }
    float* qp = (float*)(sm + O_QP);
    if (lane < 4){
        #pragma unroll
        for (int i=0;i<16;++i)
            qp[wid*64 + (i>>1)*8 + lane*2 + (i&1)] = qacc[i];
    }
    __syncthreads();

    float* slot = g_part + ((size_t)b*SPLIT_ + s)*SLOT_;
    if (tid < 64){
        float s8 = 0.0f;
        #pragma unroll
        for (int w=0;w<8;++w) s8 += qp[w*64 + tid];
        slot[tid] = s8;
    }
    // ---- write Qx / Qx2 partials (hi+lo already chained) ----
    {
        float* dmat = slot + 64 + ((nw>>1)? 4096 : 0);
        int dcb = 32*(nw&1);
        #pragma unroll
        for (int mtp=0;mtp<2;++mtp){
            #pragma unroll
            for (int cn=0;cn<2;++cn){
                #pragma unroll
                for (int h=0;h<2;++h){
                    const float* c = acc2[mtp][cn*2+h];
                    int k0 = 32*mw + 16*mtp + g;
                    int dc = dcb + cn*16 + h*8 + tg*2;
                    *(float2*)(dmat + k0*64 + dc)     = make_float2(c[0], c[1]);
                    *(float2*)(dmat + (k0+8)*64 + dc) = make_float2(c[2], c[3]);
                }
            }
        }
    }

    // ---- fused finalize: last CTA of this batch reduces + writes output ----
    __threadfence();
    __syncthreads();
    __shared__ int is_last;
    if (tid == 0){
        int old = atomicAdd(&g_cnt[b], 1);
        is_last = (old == SPLIT_-1);
    }
    __syncthreads();
    if (!is_last) return;
    __threadfence();   // acquire: other CTAs' slot writes visible

    float* qsum_s = ccs;  // reuse
    const float* base = g_part + (size_t)b*SPLIT_*SLOT_;
    const float inv_n = 1.0f/(float)N_;
    if (tid < 64){
        float ssum = 0.0f;
        #pragma unroll
        for (int t=0;t<SPLIT_;++t) ssum += base[(size_t)t*SLOT_ + tid];
        ssum *= inv_n;
        qsum_s[tid] = ssum;
        out[(size_t)b*SLOT_ + tid] = ssum - pi[tid];
    }
    __syncthreads();
    #pragma unroll
    for (int ii=0; ii<16; ++ii){
        int idx = ii*256 + tid;
        float qx=0.0f, qx2=0.0f;
        #pragma unroll
        for (int t=0;t<SPLIT_;++t){
            const float* sl = base + (size_t)t*SLOT_;
            qx  += sl[64 + idx];
            qx2 += sl[64 + 64*64 + idx];
        }
        qx *= inv_n; qx2 *= inv_n;
        float m = mu[idx], v = var[idx], qsv = qsum_s[idx>>6];
        out[(size_t)b*SLOT_ + 64 + idx] = qx - qsv*m;
        out[(size_t)b*SLOT_ + 64 + 64*64 + idx] = -qx2 - qsv*m*m + qsv*v + 2.0f*qx*m;
    }
    if (tid == 0) g_cnt[b] = 0;   // reset for next graph replay
}

extern "C" void kernel_launch(void* const* d_in, const int* in_sizes, int n_in,
                              void* d_out, int out_size)
{
    const float* x   = (const float*)d_in[0];
    const float* pi  = (const float*)d_in[1];
    const float* mu  = (const float*)d_in[2];
    const float* var = (const float*)d_in[3];
    float* out = (float*)d_out;
    cudaFuncSetAttribute(fv_main, cudaFuncAttributeMaxDynamicSharedMemorySize, SMEMSZ);
    dim3 grid(SPLIT_, B_);
    fv_main<<<grid, 256, SMEMSZ>>>(x, pi, mu, var, out);
}